// round 16
// baseline (speedup 1.0000x reference)
#include <cuda_runtime.h>
#include <math.h>

// ---------------------------------------------------------------------------
// SE4: 4x4-patch squeeze-excite. Round-3 serial structure (proven optimum):
//   pool ; mlp1 ; mlp2 ; gate     (4 launches, full-width grids)
// Gate: each thread handles FOUR fully-coalesced float4 at idx4 + k*QUARTER
// (same (c,h,w), batches b, b+2, b+6, b+6) -> 4x memory-level parallelism,
// one shared index computation, 8192 blocks.
// ---------------------------------------------------------------------------

#define B_   8
#define C_   64
#define H_   256
#define W_   256
#define SQ_  256
#define GC_  1024
#define NPOOL (B_ * GC_)
#define NT   256
#define BATCH_F4 (C_ * H_ * W_ / 4)       // 2^20 float4 per batch
#define QUARTER_F4 (2 * BATCH_F4)         // 2 batches of float4

__device__ float g_pooled[NPOOL];
__device__ float g_s[B_ * SQ_];
__device__ float g_gates[NPOOL];

// ---------------------------------------------------------------------------
__device__ __forceinline__ float mishf(float x) {
    float sp = (x > 20.0f) ? x : log1pf(__expf(x));
    return x * tanhf(sp);
}
__device__ __forceinline__ float sigmoidf_(float x) {
    return 1.0f / (1.0f + __expf(-x));
}

// ---------------------------------------------------------------------------
// Kernel 1: patch mean pool (round-1 body + 2 accumulators). One warp per
// (b,c,i,j) patch; 8192 warps = 1024 blocks x 256 threads.
// ---------------------------------------------------------------------------
__global__ void __launch_bounds__(NT) se4_pool(const float* __restrict__ t) {
    int warp = blockIdx.x * 8 + (threadIdx.x >> 5);
    int lane = threadIdx.x & 31;

    int b  = warp >> 10;
    int r  = warp & 1023;
    int c  = r >> 4;
    int ij = r & 15;
    int i  = ij >> 2;
    int j  = ij & 3;

    const float* base = t + (((size_t)(b * C_ + c) * H_ + i * 64) * W_ + j * 64);
    int row0 = lane >> 4;           // 0 or 1
    int col4 = lane & 15;           // 0..15
    const float* p = base + (size_t)row0 * W_ + col4 * 4;

    float a0 = 0.0f, a1 = 0.0f;
#pragma unroll 8
    for (int it = 0; it < 16; ++it) {
        float4 v0 = *reinterpret_cast<const float4*>(p + (size_t)(it * 4 + 0) * W_);
        float4 v1 = *reinterpret_cast<const float4*>(p + (size_t)(it * 4 + 2) * W_);
        a0 += (v0.x + v0.y) + (v0.z + v0.w);
        a1 += (v1.x + v1.y) + (v1.z + v1.w);
    }
    float acc = a0 + a1;
#pragma unroll
    for (int off = 16; off > 0; off >>= 1)
        acc += __shfl_down_sync(0xFFFFFFFFu, acc, off);

    if (lane == 0)
        g_pooled[b * GC_ + ij * C_ + c] = acc * (1.0f / 4096.0f);
}

// ---------------------------------------------------------------------------
// Kernel 2a: s = mish(pooled @ reduce_w^T + b). One warp per (b,out).
// 2048 warps = 256 blocks.
// ---------------------------------------------------------------------------
__global__ void __launch_bounds__(NT) se4_mlp1(const float* __restrict__ reduce_w,
                                               const float* __restrict__ reduce_b) {
    int warp = blockIdx.x * 8 + (threadIdx.x >> 5);
    int lane = threadIdx.x & 31;
    int b    = warp >> 8;
    int out  = warp & 255;

    const float4* wrow = reinterpret_cast<const float4*>(reduce_w + (size_t)out * GC_);
    const float4* prow = reinterpret_cast<const float4*>(g_pooled + (size_t)b * GC_);

    float acc = 0.0f;
#pragma unroll
    for (int k4 = lane; k4 < GC_ / 4; k4 += 32) {
        float4 wv = wrow[k4];
        float4 pv = prow[k4];
        acc += wv.x * pv.x + wv.y * pv.y + wv.z * pv.z + wv.w * pv.w;
    }
#pragma unroll
    for (int off = 16; off > 0; off >>= 1)
        acc += __shfl_down_sync(0xFFFFFFFFu, acc, off);
    if (lane == 0)
        g_s[b * SQ_ + out] = mishf(acc + reduce_b[out]);
}

// ---------------------------------------------------------------------------
// Kernel 2b: g = sigmoid(s @ expand_w^T + b). One warp per (b,out).
// 8192 warps = 1024 blocks.
// ---------------------------------------------------------------------------
__global__ void __launch_bounds__(NT) se4_mlp2(const float* __restrict__ expand_w,
                                               const float* __restrict__ expand_b) {
    int warp = blockIdx.x * 8 + (threadIdx.x >> 5);
    int lane = threadIdx.x & 31;
    int b    = warp >> 10;
    int out  = warp & 1023;

    const float4* wrow = reinterpret_cast<const float4*>(expand_w + (size_t)out * SQ_);
    const float4* srow = reinterpret_cast<const float4*>(g_s + (size_t)b * SQ_);

    float acc = 0.0f;
#pragma unroll
    for (int k4 = lane; k4 < SQ_ / 4; k4 += 32) {
        float4 wv = wrow[k4];
        float4 sv = srow[k4];
        acc += wv.x * sv.x + wv.y * sv.y + wv.z * sv.z + wv.w * sv.w;
    }
#pragma unroll
    for (int off = 16; off > 0; off >>= 1)
        acc += __shfl_down_sync(0xFFFFFFFFu, acc, off);
    if (lane == 0)
        g_gates[b * GC_ + out] = sigmoidf_(acc + expand_b[out]);
}

// ---------------------------------------------------------------------------
// Kernel 3: gating, 4 elements per thread. Thread handles idx4 + k*QUARTER_F4
// (same c/h/w; batches b, b+2, b+4, b+6; gate offsets +k*2*GC_).
// grid = QUARTER_F4 / NT = 8192 blocks. Reads .cs, writes .stcs.
// ---------------------------------------------------------------------------
__global__ void __launch_bounds__(NT) se4_gate(const float* __restrict__ t,
                                               float* __restrict__ out) {
    size_t idx4 = (size_t)blockIdx.x * NT + threadIdx.x;   // in [0, QUARTER_F4)
    int w4 = (int)(idx4 & 63);
    int h  = (int)(idx4 >> 6) & 255;
    int c  = (int)(idx4 >> 14) & 63;
    int b  = (int)(idx4 >> 20);                            // 0..1

    const float* gp = &g_gates[b * GC_ + (h >> 6) * 256 + (w4 >> 4) * 64 + c];
    float gate0 = __ldg(gp);
    float gate1 = __ldg(gp + 2 * GC_);
    float gate2 = __ldg(gp + 4 * GC_);
    float gate3 = __ldg(gp + 6 * GC_);

    const float4* t4 = reinterpret_cast<const float4*>(t);
    float4*       o4 = reinterpret_cast<float4*>(out);

    float4 v0 = __ldcs(t4 + idx4);
    float4 v1 = __ldcs(t4 + idx4 + 1 * QUARTER_F4);
    float4 v2 = __ldcs(t4 + idx4 + 2 * QUARTER_F4);
    float4 v3 = __ldcs(t4 + idx4 + 3 * QUARTER_F4);
    v0.x *= gate0; v0.y *= gate0; v0.z *= gate0; v0.w *= gate0;
    v1.x *= gate1; v1.y *= gate1; v1.z *= gate1; v1.w *= gate1;
    v2.x *= gate2; v2.y *= gate2; v2.z *= gate2; v2.w *= gate2;
    v3.x *= gate3; v3.y *= gate3; v3.z *= gate3; v3.w *= gate3;
    __stcs(o4 + idx4,                  v0);
    __stcs(o4 + idx4 + 1 * QUARTER_F4, v1);
    __stcs(o4 + idx4 + 2 * QUARTER_F4, v2);
    __stcs(o4 + idx4 + 3 * QUARTER_F4, v3);
}

// ---------------------------------------------------------------------------
extern "C" void kernel_launch(void* const* d_in, const int* in_sizes, int n_in,
                              void* d_out, int out_size) {
    const float* t        = (const float*)d_in[0];
    const float* reduce_w = (const float*)d_in[1];
    const float* reduce_b = (const float*)d_in[2];
    const float* expand_w = (const float*)d_in[3];
    const float* expand_b = (const float*)d_in[4];
    float* out = (float*)d_out;

    se4_pool<<<1024, NT>>>(t);
    se4_mlp1<<<256, NT>>>(reduce_w, reduce_b);
    se4_mlp2<<<1024, NT>>>(expand_w, expand_b);
    se4_gate<<<8192, NT>>>(t, out);
}

// round 17
// speedup vs baseline: 1.0010x; 1.0010x over previous
#include <cuda_runtime.h>
#include <math.h>

// ---------------------------------------------------------------------------
// SE4: 4x4-patch squeeze-excite. Converged serial structure:
//   pool ; mlp1 ; mlp2 ; gate     (4 launches, full-width grids)
// Gate = round-15 winner (2 coalesced float4/thread, batches b and b+4),
// with REVERSED block order (tail of t is the freshest L2 residue from pool).
// mlp2 computes 2 outputs per warp sharing the s-vector loads.
// ---------------------------------------------------------------------------

#define B_   8
#define C_   64
#define H_   256
#define W_   256
#define SQ_  256
#define GC_  1024
#define NPOOL (B_ * GC_)
#define NT   256
#define BATCH_F4 (C_ * H_ * W_ / 4)       // 2^20 float4 per batch
#define HALF_F4 (4 * BATCH_F4)            // 4 batches of float4

__device__ float g_pooled[NPOOL];
__device__ float g_s[B_ * SQ_];
__device__ float g_gates[NPOOL];

// ---------------------------------------------------------------------------
__device__ __forceinline__ float mishf(float x) {
    float sp = (x > 20.0f) ? x : log1pf(__expf(x));
    return x * tanhf(sp);
}
__device__ __forceinline__ float sigmoidf_(float x) {
    return 1.0f / (1.0f + __expf(-x));
}

// ---------------------------------------------------------------------------
// Kernel 1: patch mean pool (round-15 body). One warp per (b,c,i,j) patch;
// 8192 warps = 1024 blocks x 256 threads. Default policy -> fills L2.
// ---------------------------------------------------------------------------
__global__ void __launch_bounds__(NT) se4_pool(const float* __restrict__ t) {
    int warp = blockIdx.x * 8 + (threadIdx.x >> 5);
    int lane = threadIdx.x & 31;

    int b  = warp >> 10;
    int r  = warp & 1023;
    int c  = r >> 4;
    int ij = r & 15;
    int i  = ij >> 2;
    int j  = ij & 3;

    const float* base = t + (((size_t)(b * C_ + c) * H_ + i * 64) * W_ + j * 64);
    int row0 = lane >> 4;           // 0 or 1
    int col4 = lane & 15;           // 0..15
    const float* p = base + (size_t)row0 * W_ + col4 * 4;

    float a0 = 0.0f, a1 = 0.0f;
#pragma unroll 8
    for (int it = 0; it < 16; ++it) {
        float4 v0 = *reinterpret_cast<const float4*>(p + (size_t)(it * 4 + 0) * W_);
        float4 v1 = *reinterpret_cast<const float4*>(p + (size_t)(it * 4 + 2) * W_);
        a0 += (v0.x + v0.y) + (v0.z + v0.w);
        a1 += (v1.x + v1.y) + (v1.z + v1.w);
    }
    float acc = a0 + a1;
#pragma unroll
    for (int off = 16; off > 0; off >>= 1)
        acc += __shfl_down_sync(0xFFFFFFFFu, acc, off);

    if (lane == 0)
        g_pooled[b * GC_ + ij * C_ + c] = acc * (1.0f / 4096.0f);
}

// ---------------------------------------------------------------------------
// Kernel 2a: s = mish(pooled @ reduce_w^T + b). One warp per (b,out).
// 2048 warps = 256 blocks.
// ---------------------------------------------------------------------------
__global__ void __launch_bounds__(NT) se4_mlp1(const float* __restrict__ reduce_w,
                                               const float* __restrict__ reduce_b) {
    int warp = blockIdx.x * 8 + (threadIdx.x >> 5);
    int lane = threadIdx.x & 31;
    int b    = warp >> 8;
    int out  = warp & 255;

    const float4* wrow = reinterpret_cast<const float4*>(reduce_w + (size_t)out * GC_);
    const float4* prow = reinterpret_cast<const float4*>(g_pooled + (size_t)b * GC_);

    float acc = 0.0f;
#pragma unroll
    for (int k4 = lane; k4 < GC_ / 4; k4 += 32) {
        float4 wv = wrow[k4];
        float4 pv = prow[k4];
        acc += wv.x * pv.x + wv.y * pv.y + wv.z * pv.z + wv.w * pv.w;
    }
#pragma unroll
    for (int off = 16; off > 0; off >>= 1)
        acc += __shfl_down_sync(0xFFFFFFFFu, acc, off);
    if (lane == 0)
        g_s[b * SQ_ + out] = mishf(acc + reduce_b[out]);
}

// ---------------------------------------------------------------------------
// Kernel 2b: g = sigmoid(s @ expand_w^T + b). One warp per (b, 2 outputs)
// sharing the s loads. 4096 warps = 512 blocks.
// ---------------------------------------------------------------------------
__global__ void __launch_bounds__(NT) se4_mlp2(const float* __restrict__ expand_w,
                                               const float* __restrict__ expand_b) {
    int warp = blockIdx.x * 8 + (threadIdx.x >> 5);   // 0..4095
    int lane = threadIdx.x & 31;
    int b    = warp >> 9;                              // / 512
    int o0   = (warp & 511) * 2;                       // first of 2 outputs

    const float4* w0 = reinterpret_cast<const float4*>(expand_w + (size_t)o0 * SQ_);
    const float4* w1 = reinterpret_cast<const float4*>(expand_w + (size_t)(o0 + 1) * SQ_);
    const float4* srow = reinterpret_cast<const float4*>(g_s + (size_t)b * SQ_);

    float acc0 = 0.0f, acc1 = 0.0f;
#pragma unroll
    for (int k4 = lane; k4 < SQ_ / 4; k4 += 32) {
        float4 sv = srow[k4];
        float4 a  = w0[k4];
        float4 bb = w1[k4];
        acc0 += a.x  * sv.x + a.y  * sv.y + a.z  * sv.z + a.w  * sv.w;
        acc1 += bb.x * sv.x + bb.y * sv.y + bb.z * sv.z + bb.w * sv.w;
    }
#pragma unroll
    for (int off = 16; off > 0; off >>= 1) {
        acc0 += __shfl_down_sync(0xFFFFFFFFu, acc0, off);
        acc1 += __shfl_down_sync(0xFFFFFFFFu, acc1, off);
    }
    if (lane == 0) {
        g_gates[b * GC_ + o0]     = sigmoidf_(acc0 + expand_b[o0]);
        g_gates[b * GC_ + o0 + 1] = sigmoidf_(acc1 + expand_b[o0 + 1]);
    }
}

// ---------------------------------------------------------------------------
// Kernel 3: gating (round-15 winner + reversed block order). Thread handles
// idx4 (batches 0-3) and idx4 + HALF_F4 (batches 4-7, gate offset +4*GC_).
// grid = HALF_F4 / NT = 16384 blocks. Reads .cs, writes .stcs.
// Reversed order: tail of t is the freshest L2 residue from the pool pass.
// ---------------------------------------------------------------------------
__global__ void __launch_bounds__(NT) se4_gate(const float* __restrict__ t,
                                               float* __restrict__ out) {
    int bid = gridDim.x - 1 - blockIdx.x;                  // reverse sweep
    size_t idx4 = (size_t)bid * NT + threadIdx.x;          // in [0, HALF_F4)
    int w4 = (int)(idx4 & 63);
    int h  = (int)(idx4 >> 6) & 255;
    int c  = (int)(idx4 >> 14) & 63;
    int b  = (int)(idx4 >> 20);                            // 0..3

    const float* gp = &g_gates[b * GC_ + (h >> 6) * 256 + (w4 >> 4) * 64 + c];
    float gate0 = __ldg(gp);
    float gate1 = __ldg(gp + 4 * GC_);

    const float4* t4 = reinterpret_cast<const float4*>(t);
    float4*       o4 = reinterpret_cast<float4*>(out);

    float4 v0 = __ldcs(t4 + idx4);
    float4 v1 = __ldcs(t4 + idx4 + HALF_F4);
    v0.x *= gate0; v0.y *= gate0; v0.z *= gate0; v0.w *= gate0;
    v1.x *= gate1; v1.y *= gate1; v1.z *= gate1; v1.w *= gate1;
    __stcs(o4 + idx4,           v0);
    __stcs(o4 + idx4 + HALF_F4, v1);
}

// ---------------------------------------------------------------------------
extern "C" void kernel_launch(void* const* d_in, const int* in_sizes, int n_in,
                              void* d_out, int out_size) {
    const float* t        = (const float*)d_in[0];
    const float* reduce_w = (const float*)d_in[1];
    const float* reduce_b = (const float*)d_in[2];
    const float* expand_w = (const float*)d_in[3];
    const float* expand_b = (const float*)d_in[4];
    float* out = (float*)d_out;

    se4_pool<<<1024, NT>>>(t);
    se4_mlp1<<<256, NT>>>(reduce_w, reduce_b);
    se4_mlp2<<<512, NT>>>(expand_w, expand_b);
    se4_gate<<<16384, NT>>>(t, out);
}